// round 12
// baseline (speedup 1.0000x reference)
#include <cuda_runtime.h>
#include <cuda_bf16.h>
#include <math.h>
#include <stdint.h>

// Problem constants: B=4, L=2048 -> N=8192 tokens
#define NTOK 8192
#define DDIM 1024
#define HDIM 2048
#define NEXP 8
#define NSH 2
#define MAXP (2 * NTOK)
#define MAXP_PAD (MAXP + NEXP * 128)  // 17408
#define TILES_MAX (MAXP_PAD / 128)    // 136
#define MT_S (NTOK / 128)             // 64

// GEMM staging geometry (words = 32-bit packed bf16 pairs)
// CTA tile 128(M) x 256(N), BK=32 (16 kpairs). A: 128 rows, B: 256 rows, stride 20.
#define NSTG 3
#define RSTRIDE 20
#define AH_OFF 0
#define AL_OFF 2560                    // 128*20
#define BH_OFF 5120
#define BL_OFF 10240                   // 5120 + 256*20
#define STG_W 15360                    // words per stage (60KB)
#define SMEMSZ (NSTG * STG_W * 4)      // 184320 bytes

// ------------------------- scratch (__device__ globals) -------------------------
__device__ unsigned g_x_hi [(size_t)NTOK * 512];
__device__ unsigned g_x_lo [(size_t)NTOK * 512];
__device__ unsigned g_xg_hi[(size_t)MAXP_PAD * 512];
__device__ unsigned g_xg_lo[(size_t)MAXP_PAD * 512];
__device__ unsigned g_h_hi [(size_t)MAXP_PAD * 1024];
__device__ unsigned g_h_lo [(size_t)MAXP_PAD * 1024];
__device__ unsigned g_hs_hi[(size_t)NSH * NTOK * 1024];
__device__ unsigned g_hs_lo[(size_t)NSH * NTOK * 1024];
__device__ unsigned g_w1t_hi[(size_t)NEXP * 512 * HDIM];
__device__ unsigned g_w1t_lo[(size_t)NEXP * 512 * HDIM];
__device__ unsigned g_w2t_hi[(size_t)NEXP * 1024 * DDIM];
__device__ unsigned g_w2t_lo[(size_t)NEXP * 1024 * DDIM];
__device__ unsigned g_s1t_hi[(size_t)NSH * 512 * HDIM];
__device__ unsigned g_s1t_lo[(size_t)NSH * 512 * HDIM];
__device__ unsigned g_s2t_hi[(size_t)NSH * 1024 * DDIM];
__device__ unsigned g_s2t_lo[(size_t)NSH * 1024 * DDIM];
__device__ float g_ybuf[(size_t)MAXP_PAD * DDIM];
__device__ float g_ys[(size_t)NSH * NTOK * DDIM];
__device__ int   g_pair_token[MAXP_PAD];
__device__ int   g_slot_of[MAXP];
__device__ float g_gate[MAXP];
__device__ int   g_topi[MAXP];
__device__ int   g_tile_expert[TILES_MAX];

// ------------------------- helpers -------------------------
__device__ __forceinline__ uint32_t smem_u32(const void* p) {
    uint32_t a;
    asm("{ .reg .u64 t; cvta.to.shared.u64 t, %1; cvt.u32.u64 %0, t; }" : "=r"(a) : "l"(p));
    return a;
}
__device__ __forceinline__ void cp16(uint32_t dst, const void* src) {
    asm volatile("cp.async.cg.shared.global [%0], [%1], 16;" :: "r"(dst), "l"(src) : "memory");
}
#define CP_COMMIT() asm volatile("cp.async.commit_group;" ::: "memory")
#define CP_WAIT1() asm volatile("cp.async.wait_group 1;" ::: "memory")

#define LDSM4(r0, r1, r2, r3, addr)                                           \
    asm volatile("ldmatrix.sync.aligned.m8n8.x4.shared.b16 {%0,%1,%2,%3},[%4];" \
                 : "=r"(r0), "=r"(r1), "=r"(r2), "=r"(r3) : "r"(addr))
#define LDSM2(r0, r1, addr)                                                   \
    asm volatile("ldmatrix.sync.aligned.m8n8.x2.shared.b16 {%0,%1},[%2];"     \
                 : "=r"(r0), "=r"(r1) : "r"(addr))

__device__ __forceinline__ void cvt_pair(float x0, float x1, unsigned& hi, unsigned& lo) {
    __nv_bfloat16 h0 = __float2bfloat16(x0);
    __nv_bfloat16 h1 = __float2bfloat16(x1);
    float r0 = x0 - __bfloat162float(h0);
    float r1 = x1 - __bfloat162float(h1);
    __nv_bfloat16 l0 = __float2bfloat16(r0);
    __nv_bfloat16 l1 = __float2bfloat16(r1);
    hi = (unsigned)__bfloat16_as_ushort(h0) | ((unsigned)__bfloat16_as_ushort(h1) << 16);
    lo = (unsigned)__bfloat16_as_ushort(l0) | ((unsigned)__bfloat16_as_ushort(l1) << 16);
}

#define MMA_BF16(accp, a, b)                                                  \
    asm volatile(                                                             \
        "mma.sync.aligned.m16n8k16.row.col.f32.bf16.bf16.f32 "                \
        "{%0,%1,%2,%3},{%4,%5,%6,%7},{%8,%9},{%0,%1,%2,%3};"                  \
        : "+f"((accp)[0]), "+f"((accp)[1]), "+f"((accp)[2]), "+f"((accp)[3])  \
        : "r"((a)[0]), "r"((a)[1]), "r"((a)[2]), "r"((a)[3]),                 \
          "r"((b)[0]), "r"((b)[1]))

// ------------------------- router -------------------------
__global__ void router_kernel(const float* __restrict__ x, const float* __restrict__ rw,
                              const float* __restrict__ rb, int N) {
    int w = (blockIdx.x * blockDim.x + threadIdx.x) >> 5;
    int lane = threadIdx.x & 31;
    if (w >= N) return;
    const float* xr = x + (size_t)w * DDIM;
    float acc[NEXP];
#pragma unroll
    for (int e = 0; e < NEXP; e++) acc[e] = 0.f;
    for (int d = lane; d < DDIM; d += 32) {
        float xv = xr[d];
        const float* r = rw + (size_t)d * NEXP;
#pragma unroll
        for (int e = 0; e < NEXP; e++) acc[e] = fmaf(xv, r[e], acc[e]);
    }
#pragma unroll
    for (int e = 0; e < NEXP; e++)
        for (int o = 16; o > 0; o >>= 1) acc[e] += __shfl_xor_sync(0xffffffffu, acc[e], o);
    if (lane == 0) {
        float v0 = -1e30f, v1 = -1e30f;
        int i0 = 0, i1 = 0;
#pragma unroll
        for (int e = 0; e < NEXP; e++) {
            float v = acc[e] + rb[e];
            if (v > v0) { v1 = v0; i1 = i0; v0 = v; i0 = e; }
            else if (v > v1) { v1 = v; i1 = e; }
        }
        float p1 = expf(v1 - v0);
        float inv = 1.0f / (1.0f + p1);
        g_topi[2 * w] = i0; g_topi[2 * w + 1] = i1;
        g_gate[2 * w] = inv; g_gate[2 * w + 1] = p1 * inv;
    }
}

// ------------------------- bucketing -------------------------
__global__ void bucket_kernel(int N) {
    __shared__ int s_cnt[NEXP];
    __shared__ int s_off[NEXP + 1];
    __shared__ int s_c2[NEXP];
    int tid = threadIdx.x;
    if (tid < NEXP) { s_cnt[tid] = 0; s_c2[tid] = 0; }
    __syncthreads();
    int P = 2 * N;
    for (int p = tid; p < P; p += blockDim.x) atomicAdd(&s_cnt[g_topi[p]], 1);
    for (int i = tid; i < MAXP_PAD; i += blockDim.x) g_pair_token[i] = -1;
    __syncthreads();
    if (tid == 0) {
        int o = 0;
        for (int e = 0; e < NEXP; e++) { s_off[e] = o; o += ((s_cnt[e] + 127) >> 7) << 7; }
        s_off[NEXP] = o;
        int total = o >> 7;
        for (int t = 0; t < TILES_MAX; t++) {
            int ex = -1;
            if (t < total) {
                int s = t << 7;
                for (int e = 0; e < NEXP; e++)
                    if (s >= s_off[e] && s < s_off[e + 1]) ex = e;
            }
            g_tile_expert[t] = ex;
        }
    }
    __syncthreads();
    for (int p = tid; p < P; p += blockDim.x) {
        int e = g_topi[p];
        int pos = atomicAdd(&s_c2[e], 1);
        int slot = s_off[e] + pos;
        g_pair_token[slot] = p >> 1;
        g_slot_of[p] = slot;
    }
}

// ------------------------- operand pre-conversion -------------------------
// x (fp32 row-major) -> packed bf16 hi/lo words, row-major [n][D/2]
__global__ void pack_x_kernel(const float* __restrict__ x) {
    size_t idx = (size_t)blockIdx.x * blockDim.x + threadIdx.x;
    if (idx >= (size_t)NTOK * 512) return;
    float2 v = *(const float2*)(x + 2 * idx);
    unsigned h, l; cvt_pair(v.x, v.y, h, l);
    g_x_hi[idx] = h; g_x_lo[idx] = l;
}
// gathered x by slot -> [slot][D/2]
__global__ void pack_xg_kernel(const float* __restrict__ x) {
    size_t idx = (size_t)blockIdx.x * blockDim.x + threadIdx.x;
    if (idx >= (size_t)MAXP_PAD * 512) return;
    int slot = (int)(idx >> 9), w = (int)(idx & 511);
    int tok = g_pair_token[slot];
    float2 v = (tok >= 0) ? *(const float2*)(x + (size_t)tok * DDIM + 2 * w)
                          : make_float2(0.f, 0.f);
    unsigned h, l; cvt_pair(v.x, v.y, h, l);
    g_xg_hi[idx] = h; g_xg_lo[idx] = l;
}
// W [Z][K][N] fp32 -> n-major blocks [(z*NT+nt)*KC + kc][n 256][kpair 16] packed hi/lo
__global__ void wt_kernel(const float* __restrict__ W,
                          unsigned* __restrict__ oh, unsigned* __restrict__ ol,
                          int K, int N) {
    __shared__ float t[64][33];
    int z = blockIdx.z;
    const float* Wz = W + (size_t)z * K * N;
    int k0 = blockIdx.y * 64, n0 = blockIdx.x * 32;
    int tx = threadIdx.x, ty = threadIdx.y;
#pragma unroll
    for (int i = 0; i < 8; i++) {
        int k = ty + i * 8;
        t[k][tx] = Wz[(size_t)(k0 + k) * N + n0 + tx];
    }
    __syncthreads();
    int tid = ty * 32 + tx;
    int nl = tid >> 3, w8 = tid & 7;
    int NT = N >> 8, KC = K >> 5;
    int nabs = n0 + nl, nt = nabs >> 8, nin = nabs & 255;
#pragma unroll
    for (int kcb = 0; kcb < 2; kcb++) {
        int kc = (k0 >> 5) + kcb;
        size_t base = ((size_t)(z * NT + nt) * KC + kc) * 4096 + (size_t)nin * 16;
#pragma unroll
        for (int j = 0; j < 2; j++) {
            int kp = w8 * 2 + j;
            int kloc = kcb * 32 + kp * 2;
            unsigned h, l; cvt_pair(t[kloc][nl], t[kloc + 1][nl], h, l);
            oh[base + kp] = h; ol[base + kp] = l;
        }
    }
}

// ------------------------- mma.sync GEMM: 128x256 CTA tile, 64x64 per warp -------------------------
// 256 threads = 8 warps (2 in M x 4 in N), BK=32 (16 kpairs), bf16x3 (HH+HL+LH),
// 3-stage cp.async, ldmatrix fragment loads.
// GELU=0: C fp32 += bias. GELU=1: gelu(C+bias) -> packed bf16 hi/lo words (A-format).
template <int GELU>
__global__ void __launch_bounds__(256, 1)
mma_gemm2(const unsigned* __restrict__ Ah, const unsigned* __restrict__ Al,
          long long a_z, int a_ld,
          const unsigned* __restrict__ Bh, const unsigned* __restrict__ Bl,
          const float* __restrict__ bias_base, int bias_stride,
          float* __restrict__ Cf, long long c_z, int c_ld,
          unsigned* __restrict__ Oh, unsigned* __restrict__ Ol,
          long long o_z, int o_ld,
          const int* __restrict__ te, int nKb, int NTtot) {
    int nt = blockIdx.x, mt = blockIdx.y, z = blockIdx.z;
    int expert = te ? te[mt] : z;
    if (expert < 0) return;

    extern __shared__ unsigned smw[];
    uint32_t sb = smem_u32(smw);
    int tid = threadIdx.x, lane = tid & 31, wid = tid >> 5;
    int wm = (wid & 1) * 64, wn = (wid >> 1) * 64;
    int mBase = mt * 128;

    const unsigned* Abase_h = Ah + (size_t)z * a_z + (size_t)mBase * a_ld;
    const unsigned* Abase_l = Al + (size_t)z * a_z + (size_t)mBase * a_ld;
    const unsigned* Bbase_h = Bh + (size_t)(expert * NTtot + nt) * nKb * 4096;
    const unsigned* Bbase_l = Bl + (size_t)(expert * NTtot + nt) * nKb * 4096;

    // copy decode: A 128 rows x 16 words (2 cp16/thread per array), B 256 rows x 16 words (4 cp16/thread)
    int rowA = tid >> 1, c4 = (tid & 1) * 8;
    int rowB = tid;

    auto issue = [&](int kb) {
        uint32_t st = sb + (uint32_t)((kb % NSTG) * STG_W) * 4;
        const unsigned* arh = Abase_h + (size_t)rowA * a_ld + kb * 16 + c4;
        const unsigned* arl = Abase_l + (size_t)rowA * a_ld + kb * 16 + c4;
        uint32_t da = st + (AH_OFF + rowA * RSTRIDE + c4) * 4;
        cp16(da, arh); cp16(da + 16, arh + 4);
        uint32_t dal = st + (AL_OFF + rowA * RSTRIDE + c4) * 4;
        cp16(dal, arl); cp16(dal + 16, arl + 4);
        const unsigned* brh = Bbase_h + (size_t)kb * 4096 + (size_t)rowB * 16;
        const unsigned* brl = Bbase_l + (size_t)kb * 4096 + (size_t)rowB * 16;
        uint32_t db = st + (BH_OFF + rowB * RSTRIDE) * 4;
        cp16(db, brh); cp16(db + 16, brh + 4);
        cp16(db + 32, brh + 8); cp16(db + 48, brh + 12);
        uint32_t dbl = st + (BL_OFF + rowB * RSTRIDE) * 4;
        cp16(dbl, brl); cp16(dbl + 16, brl + 4);
        cp16(dbl + 32, brl + 8); cp16(dbl + 48, brl + 12);
    };

    float acc[4][8][4];
#pragma unroll
    for (int a = 0; a < 4; a++)
#pragma unroll
        for (int b = 0; b < 8; b++)
#pragma unroll
            for (int c = 0; c < 4; c++) acc[a][b][c] = 0.f;

    // prologue: 2 stages in flight
    issue(0); CP_COMMIT();
    if (nKb > 1) issue(1);
    CP_COMMIT();

    // ldmatrix per-thread base offsets (bytes)
    // A x4: lanes 0-15 -> rows 0-15 (k half 0), lanes 16-31 -> rows 0-15 (k half 1)
    uint32_t a_off = (uint32_t)((wm + (lane & 15)) * RSTRIDE + (lane >> 4) * 4) * 4;
    // B x2: lanes 0-7 -> n rows (k half 0), lanes 8-15 -> n rows (k half 1)
    uint32_t b_off = (uint32_t)((wn + (lane & 7)) * RSTRIDE + ((lane >> 3) & 1) * 4) * 4;

    for (int kb = 0; kb < nKb; kb++) {
        CP_WAIT1();
        __syncthreads();
        int nx = kb + 2;
        if (nx < nKb) issue(nx);
        CP_COMMIT();

        uint32_t stg = sb + (uint32_t)((kb % NSTG) * STG_W) * 4;
        uint32_t aH = stg + AH_OFF * 4 + a_off;
        uint32_t aL = stg + AL_OFF * 4 + a_off;
        uint32_t bH = stg + BH_OFF * 4 + b_off;
        uint32_t bL = stg + BL_OFF * 4 + b_off;
#pragma unroll
        for (int ks = 0; ks < 2; ks++) {
            unsigned ah[4][4], al[4][4];
#pragma unroll
            for (int mt4 = 0; mt4 < 4; mt4++) {
                uint32_t o = mt4 * (16 * RSTRIDE * 4) + ks * 32;
                LDSM4(ah[mt4][0], ah[mt4][1], ah[mt4][2], ah[mt4][3], aH + o);
                LDSM4(al[mt4][0], al[mt4][1], al[mt4][2], al[mt4][3], aL + o);
            }
#pragma unroll
            for (int n8 = 0; n8 < 8; n8++) {
                unsigned bh[2], bl[2];
                uint32_t o = n8 * (8 * RSTRIDE * 4) + ks * 32;
                LDSM2(bh[0], bh[1], bH + o);
                LDSM2(bl[0], bl[1], bL + o);
#pragma unroll
                for (int mt4 = 0; mt4 < 4; mt4++) MMA_BF16(acc[mt4][n8], ah[mt4], bh);
#pragma unroll
                for (int mt4 = 0; mt4 < 4; mt4++) MMA_BF16(acc[mt4][n8], ah[mt4], bl);
#pragma unroll
                for (int mt4 = 0; mt4 < 4; mt4++) MMA_BF16(acc[mt4][n8], al[mt4], bh);
            }
        }
    }

    // epilogue
    const float* bias = bias_base + (size_t)expert * bias_stride + nt * 256;
#pragma unroll
    for (int mt4 = 0; mt4 < 4; mt4++) {
#pragma unroll
        for (int n8 = 0; n8 < 8; n8++) {
            int row0 = mBase + wm + mt4 * 16 + (lane >> 2);
            int c0 = wn + n8 * 8 + (lane & 3) * 2;
            float b0 = bias[c0], b1 = bias[c0 + 1];
            float v0 = acc[mt4][n8][0] + b0;
            float v1 = acc[mt4][n8][1] + b1;
            float v2 = acc[mt4][n8][2] + b0;
            float v3 = acc[mt4][n8][3] + b1;
            if (GELU) {
                v0 = 0.5f * v0 * (1.0f + erff(v0 * 0.70710678118654752f));
                v1 = 0.5f * v1 * (1.0f + erff(v1 * 0.70710678118654752f));
                v2 = 0.5f * v2 * (1.0f + erff(v2 * 0.70710678118654752f));
                v3 = 0.5f * v3 * (1.0f + erff(v3 * 0.70710678118654752f));
                unsigned h0, l0, h1, l1;
                cvt_pair(v0, v1, h0, l0);
                cvt_pair(v2, v3, h1, l1);
                size_t w = (size_t)((nt * 256 + c0) >> 1);
                size_t b0i = (size_t)z * o_z + (size_t)row0 * o_ld + w;
                size_t b1i = b0i + (size_t)8 * o_ld;
                Oh[b0i] = h0; Ol[b0i] = l0;
                Oh[b1i] = h1; Ol[b1i] = l1;
            } else {
                size_t base = (size_t)z * c_z + (size_t)row0 * c_ld + nt * 256 + c0;
                *(float2*)&Cf[base] = make_float2(v0, v1);
                *(float2*)&Cf[base + (size_t)8 * c_ld] = make_float2(v2, v3);
            }
        }
    }
}

// ------------------------- final combine -------------------------
__global__ void combine_kernel(float* __restrict__ out, int N) {
    int idx = blockIdx.x * blockDim.x + threadIdx.x;
    int total = N * (DDIM / 4);
    if (idx >= total) return;
    int n = idx / (DDIM / 4);
    int d = (idx % (DDIM / 4)) * 4;
    const float4 s0 = *(const float4*)&g_ys[(size_t)n * DDIM + d];
    const float4 s1 = *(const float4*)&g_ys[(size_t)N * DDIM + (size_t)n * DDIM + d];
    int sl0 = g_slot_of[2 * n], sl1 = g_slot_of[2 * n + 1];
    float w0 = g_gate[2 * n], w1 = g_gate[2 * n + 1];
    const float4 y0 = *(const float4*)&g_ybuf[(size_t)sl0 * DDIM + d];
    const float4 y1 = *(const float4*)&g_ybuf[(size_t)sl1 * DDIM + d];
    const float inv_s = 1.0f / NSH;
    float4 o;
    o.x = inv_s * (s0.x + s1.x) + w0 * y0.x + w1 * y1.x;
    o.y = inv_s * (s0.y + s1.y) + w0 * y0.y + w1 * y1.y;
    o.z = inv_s * (s0.z + s1.z) + w0 * y0.z + w1 * y1.z;
    o.w = inv_s * (s0.w + s1.w) + w0 * y0.w + w1 * y1.w;
    *(float4*)&out[(size_t)n * DDIM + d] = o;
}

// ------------------------- launch -------------------------
#define SYM(p, s) void* p; cudaGetSymbolAddress(&p, s)

extern "C" void kernel_launch(void* const* d_in, const int* in_sizes, int n_in,
                              void* d_out, int out_size) {
    const float* x   = (const float*)d_in[0];
    const float* rw  = (const float*)d_in[1];
    const float* rb  = (const float*)d_in[2];
    const float* w1  = (const float*)d_in[3];
    const float* b1  = (const float*)d_in[4];
    const float* w2  = (const float*)d_in[5];
    const float* b2  = (const float*)d_in[6];
    const float* sw1 = (const float*)d_in[7];
    const float* sb1 = (const float*)d_in[8];
    const float* sw2 = (const float*)d_in[9];
    const float* sb2 = (const float*)d_in[10];
    float* out = (float*)d_out;
    int N = in_sizes[0] / DDIM;

    cudaFuncSetAttribute(mma_gemm2<0>, cudaFuncAttributeMaxDynamicSharedMemorySize, SMEMSZ);
    cudaFuncSetAttribute(mma_gemm2<1>, cudaFuncAttributeMaxDynamicSharedMemorySize, SMEMSZ);

    SYM(p_xh, g_x_hi);    SYM(p_xl, g_x_lo);
    SYM(p_gh, g_xg_hi);   SYM(p_gl, g_xg_lo);
    SYM(p_hh, g_h_hi);    SYM(p_hl, g_h_lo);
    SYM(p_sh, g_hs_hi);   SYM(p_sl, g_hs_lo);
    SYM(p_w1h, g_w1t_hi); SYM(p_w1l, g_w1t_lo);
    SYM(p_w2h, g_w2t_hi); SYM(p_w2l, g_w2t_lo);
    SYM(p_s1h, g_s1t_hi); SYM(p_s1l, g_s1t_lo);
    SYM(p_s2h, g_s2t_hi); SYM(p_s2l, g_s2t_lo);
    SYM(p_yb, g_ybuf);    SYM(p_ys, g_ys);
    SYM(p_te, g_tile_expert);

    // 1) router + bucketing
    router_kernel<<<(N + 7) / 8, 256>>>(x, rw, rb, N);
    bucket_kernel<<<1, 256>>>(N);
    // 2) operand pre-conversion
    pack_x_kernel<<<(NTOK * 512 + 255) / 256, 256>>>(x);
    pack_xg_kernel<<<(MAXP_PAD * 512 + 255) / 256, 256>>>(x);
    dim3 tb(32, 8);
    wt_kernel<<<dim3(HDIM / 32, DDIM / 64, NEXP), tb>>>(w1, (unsigned*)p_w1h, (unsigned*)p_w1l, DDIM, HDIM);
    wt_kernel<<<dim3(DDIM / 32, HDIM / 64, NEXP), tb>>>(w2, (unsigned*)p_w2h, (unsigned*)p_w2l, HDIM, DDIM);
    wt_kernel<<<dim3(HDIM / 32, DDIM / 64, NSH), tb>>>(sw1, (unsigned*)p_s1h, (unsigned*)p_s1l, DDIM, HDIM);
    wt_kernel<<<dim3(DDIM / 32, HDIM / 64, NSH), tb>>>(sw2, (unsigned*)p_s2h, (unsigned*)p_s2l, HDIM, DDIM);
    // 3) routed GEMM1: h = gelu(xg @ w1[e] + b1[e]) -> packed bf16 (A-format)
    mma_gemm2<1><<<dim3(HDIM / 256, TILES_MAX, 1), 256, SMEMSZ>>>(
        (unsigned*)p_gh, (unsigned*)p_gl, 0, 512,
        (unsigned*)p_w1h, (unsigned*)p_w1l, b1, HDIM,
        nullptr, 0, 0, (unsigned*)p_hh, (unsigned*)p_hl, 0, 1024,
        (const int*)p_te, DDIM / 32, HDIM / 256);
    // 4) routed GEMM2: y = h @ w2[e] + b2[e] -> fp32
    mma_gemm2<0><<<dim3(DDIM / 256, TILES_MAX, 1), 256, SMEMSZ>>>(
        (unsigned*)p_hh, (unsigned*)p_hl, 0, 1024,
        (unsigned*)p_w2h, (unsigned*)p_w2l, b2, DDIM,
        (float*)p_yb, 0, DDIM, nullptr, nullptr, 0, 0,
        (const int*)p_te, HDIM / 32, DDIM / 256);
    // 5) shared GEMM1: hs[s] = gelu(x @ sw1[s] + sb1[s]) -> packed bf16
    //    A (x) is the SAME for both shared experts -> a_z stride 0.
    mma_gemm2<1><<<dim3(HDIM / 256, MT_S, NSH), 256, SMEMSZ>>>(
        (unsigned*)p_xh, (unsigned*)p_xl, 0, 512,
        (unsigned*)p_s1h, (unsigned*)p_s1l, sb1, HDIM,
        nullptr, 0, 0, (unsigned*)p_sh, (unsigned*)p_sl, (long long)NTOK * 1024, 1024,
        nullptr, DDIM / 32, HDIM / 256);
    // 6) shared GEMM2: ys[s] = hs[s] @ sw2[s] + sb2[s] -> fp32
    mma_gemm2<0><<<dim3(DDIM / 256, MT_S, NSH), 256, SMEMSZ>>>(
        (unsigned*)p_sh, (unsigned*)p_sl, (long long)NTOK * 1024, 1024,
        (unsigned*)p_s2h, (unsigned*)p_s2l, sb2, DDIM,
        (float*)p_ys, (long long)NTOK * DDIM, DDIM, nullptr, nullptr, 0, 0,
        nullptr, HDIM / 32, DDIM / 256);
    // 7) combine
    combine_kernel<<<(N * (DDIM / 4) + 255) / 256, 256>>>(out, N);
}

// round 13
// speedup vs baseline: 1.1968x; 1.1968x over previous
#include <cuda_runtime.h>
#include <cuda_bf16.h>
#include <math.h>
#include <stdint.h>

// Problem constants: B=4, L=2048 -> N=8192 tokens
#define NTOK 8192
#define DDIM 1024
#define HDIM 2048
#define NEXP 8
#define NSH 2
#define MAXP (2 * NTOK)
#define MAXP_PAD (MAXP + NEXP * 128)  // 17408
#define TILES_MAX (MAXP_PAD / 128)    // 136
#define MT_S (NTOK / 128)             // 64

// GEMM staging geometry (words = 32-bit packed bf16 pairs)
// CTA tile 128x128, BK=32 (16 kpairs). A and B: 128 rows x 16 words, stride 20.
#define NSTG 4
#define RSTRIDE 20
#define AH_OFF 0
#define AL_OFF 2560                    // 128*20
#define BH_OFF 5120
#define BL_OFF 7680
#define STG_W 10240                    // words per stage (40KB)
#define SMEMSZ (NSTG * STG_W * 4)      // 163840 bytes

// ------------------------- scratch (__device__ globals) -------------------------
__device__ unsigned g_x_hi [(size_t)NTOK * 512];
__device__ unsigned g_x_lo [(size_t)NTOK * 512];
__device__ unsigned g_xg_hi[(size_t)MAXP_PAD * 512];
__device__ unsigned g_xg_lo[(size_t)MAXP_PAD * 512];
__device__ unsigned g_h_hi [(size_t)MAXP_PAD * 1024];
__device__ unsigned g_h_lo [(size_t)MAXP_PAD * 1024];
__device__ unsigned g_hs_hi[(size_t)NSH * NTOK * 1024];
__device__ unsigned g_hs_lo[(size_t)NSH * NTOK * 1024];
__device__ unsigned g_w1t_hi[(size_t)NEXP * 512 * HDIM];
__device__ unsigned g_w1t_lo[(size_t)NEXP * 512 * HDIM];
__device__ unsigned g_w2t_hi[(size_t)NEXP * 1024 * DDIM];
__device__ unsigned g_w2t_lo[(size_t)NEXP * 1024 * DDIM];
__device__ unsigned g_s1t_hi[(size_t)NSH * 512 * HDIM];
__device__ unsigned g_s1t_lo[(size_t)NSH * 512 * HDIM];
__device__ unsigned g_s2t_hi[(size_t)NSH * 1024 * DDIM];
__device__ unsigned g_s2t_lo[(size_t)NSH * 1024 * DDIM];
__device__ float g_ybuf[(size_t)MAXP_PAD * DDIM];
__device__ float g_ys[(size_t)NSH * NTOK * DDIM];
__device__ int   g_pair_token[MAXP_PAD];
__device__ int   g_slot_of[MAXP];
__device__ float g_gate[MAXP];
__device__ int   g_topi[MAXP];
__device__ int   g_tile_expert[TILES_MAX];

// ------------------------- helpers -------------------------
__device__ __forceinline__ uint32_t smem_u32(const void* p) {
    uint32_t a;
    asm("{ .reg .u64 t; cvta.to.shared.u64 t, %1; cvt.u32.u64 %0, t; }" : "=r"(a) : "l"(p));
    return a;
}
__device__ __forceinline__ void cp16(uint32_t dst, const void* src) {
    asm volatile("cp.async.cg.shared.global [%0], [%1], 16;" :: "r"(dst), "l"(src) : "memory");
}
#define CP_COMMIT() asm volatile("cp.async.commit_group;" ::: "memory")
#define CP_WAIT2() asm volatile("cp.async.wait_group 2;" ::: "memory")

#define LDSM4(r0, r1, r2, r3, addr)                                           \
    asm volatile("ldmatrix.sync.aligned.m8n8.x4.shared.b16 {%0,%1,%2,%3},[%4];" \
                 : "=r"(r0), "=r"(r1), "=r"(r2), "=r"(r3) : "r"(addr))
#define LDSM2(r0, r1, addr)                                                   \
    asm volatile("ldmatrix.sync.aligned.m8n8.x2.shared.b16 {%0,%1},[%2];"     \
                 : "=r"(r0), "=r"(r1) : "r"(addr))

__device__ __forceinline__ void cvt_pair(float x0, float x1, unsigned& hi, unsigned& lo) {
    __nv_bfloat16 h0 = __float2bfloat16(x0);
    __nv_bfloat16 h1 = __float2bfloat16(x1);
    float r0 = x0 - __bfloat162float(h0);
    float r1 = x1 - __bfloat162float(h1);
    __nv_bfloat16 l0 = __float2bfloat16(r0);
    __nv_bfloat16 l1 = __float2bfloat16(r1);
    hi = (unsigned)__bfloat16_as_ushort(h0) | ((unsigned)__bfloat16_as_ushort(h1) << 16);
    lo = (unsigned)__bfloat16_as_ushort(l0) | ((unsigned)__bfloat16_as_ushort(l1) << 16);
}

#define MMA_BF16(accp, a, b)                                                  \
    asm volatile(                                                             \
        "mma.sync.aligned.m16n8k16.row.col.f32.bf16.bf16.f32 "                \
        "{%0,%1,%2,%3},{%4,%5,%6,%7},{%8,%9},{%0,%1,%2,%3};"                  \
        : "+f"((accp)[0]), "+f"((accp)[1]), "+f"((accp)[2]), "+f"((accp)[3])  \
        : "r"((a)[0]), "r"((a)[1]), "r"((a)[2]), "r"((a)[3]),                 \
          "r"((b)[0]), "r"((b)[1]))

// ------------------------- router -------------------------
__global__ void router_kernel(const float* __restrict__ x, const float* __restrict__ rw,
                              const float* __restrict__ rb, int N) {
    int w = (blockIdx.x * blockDim.x + threadIdx.x) >> 5;
    int lane = threadIdx.x & 31;
    if (w >= N) return;
    const float* xr = x + (size_t)w * DDIM;
    float acc[NEXP];
#pragma unroll
    for (int e = 0; e < NEXP; e++) acc[e] = 0.f;
    for (int d = lane; d < DDIM; d += 32) {
        float xv = xr[d];
        const float* r = rw + (size_t)d * NEXP;
#pragma unroll
        for (int e = 0; e < NEXP; e++) acc[e] = fmaf(xv, r[e], acc[e]);
    }
#pragma unroll
    for (int e = 0; e < NEXP; e++)
        for (int o = 16; o > 0; o >>= 1) acc[e] += __shfl_xor_sync(0xffffffffu, acc[e], o);
    if (lane == 0) {
        float v0 = -1e30f, v1 = -1e30f;
        int i0 = 0, i1 = 0;
#pragma unroll
        for (int e = 0; e < NEXP; e++) {
            float v = acc[e] + rb[e];
            if (v > v0) { v1 = v0; i1 = i0; v0 = v; i0 = e; }
            else if (v > v1) { v1 = v; i1 = e; }
        }
        float p1 = expf(v1 - v0);
        float inv = 1.0f / (1.0f + p1);
        g_topi[2 * w] = i0; g_topi[2 * w + 1] = i1;
        g_gate[2 * w] = inv; g_gate[2 * w + 1] = p1 * inv;
    }
}

// ------------------------- bucketing -------------------------
__global__ void bucket_kernel(int N) {
    __shared__ int s_cnt[NEXP];
    __shared__ int s_off[NEXP + 1];
    __shared__ int s_c2[NEXP];
    int tid = threadIdx.x;
    if (tid < NEXP) { s_cnt[tid] = 0; s_c2[tid] = 0; }
    __syncthreads();
    int P = 2 * N;
    for (int p = tid; p < P; p += blockDim.x) atomicAdd(&s_cnt[g_topi[p]], 1);
    for (int i = tid; i < MAXP_PAD; i += blockDim.x) g_pair_token[i] = -1;
    __syncthreads();
    if (tid == 0) {
        int o = 0;
        for (int e = 0; e < NEXP; e++) { s_off[e] = o; o += ((s_cnt[e] + 127) >> 7) << 7; }
        s_off[NEXP] = o;
        int total = o >> 7;
        for (int t = 0; t < TILES_MAX; t++) {
            int ex = -1;
            if (t < total) {
                int s = t << 7;
                for (int e = 0; e < NEXP; e++)
                    if (s >= s_off[e] && s < s_off[e + 1]) ex = e;
            }
            g_tile_expert[t] = ex;
        }
    }
    __syncthreads();
    for (int p = tid; p < P; p += blockDim.x) {
        int e = g_topi[p];
        int pos = atomicAdd(&s_c2[e], 1);
        int slot = s_off[e] + pos;
        g_pair_token[slot] = p >> 1;
        g_slot_of[p] = slot;
    }
}

// ------------------------- operand pre-conversion -------------------------
// x (fp32 row-major) -> packed bf16 hi/lo words, row-major [n][D/2]
__global__ void pack_x_kernel(const float* __restrict__ x) {
    size_t idx = (size_t)blockIdx.x * blockDim.x + threadIdx.x;
    if (idx >= (size_t)NTOK * 512) return;
    float2 v = *(const float2*)(x + 2 * idx);
    unsigned h, l; cvt_pair(v.x, v.y, h, l);
    g_x_hi[idx] = h; g_x_lo[idx] = l;
}
// gathered x by slot -> [slot][D/2]
__global__ void pack_xg_kernel(const float* __restrict__ x) {
    size_t idx = (size_t)blockIdx.x * blockDim.x + threadIdx.x;
    if (idx >= (size_t)MAXP_PAD * 512) return;
    int slot = (int)(idx >> 9), w = (int)(idx & 511);
    int tok = g_pair_token[slot];
    float2 v = (tok >= 0) ? *(const float2*)(x + (size_t)tok * DDIM + 2 * w)
                          : make_float2(0.f, 0.f);
    unsigned h, l; cvt_pair(v.x, v.y, h, l);
    g_xg_hi[idx] = h; g_xg_lo[idx] = l;
}
// W [Z][K][N] fp32 -> n-major blocks [(z*NT+nt)*KC + kc][n 128][kpair 16] packed hi/lo
__global__ void wt_kernel(const float* __restrict__ W,
                          unsigned* __restrict__ oh, unsigned* __restrict__ ol,
                          int K, int N) {
    __shared__ float t[64][33];
    int z = blockIdx.z;
    const float* Wz = W + (size_t)z * K * N;
    int k0 = blockIdx.y * 64, n0 = blockIdx.x * 32;
    int tx = threadIdx.x, ty = threadIdx.y;
#pragma unroll
    for (int i = 0; i < 8; i++) {
        int k = ty + i * 8;
        t[k][tx] = Wz[(size_t)(k0 + k) * N + n0 + tx];
    }
    __syncthreads();
    int tid = ty * 32 + tx;
    int nl = tid >> 3, w8 = tid & 7;
    int NT = N >> 7, KC = K >> 5;
    int nabs = n0 + nl, nt = nabs >> 7, nin = nabs & 127;
#pragma unroll
    for (int kcb = 0; kcb < 2; kcb++) {
        int kc = (k0 >> 5) + kcb;
        size_t base = ((size_t)(z * NT + nt) * KC + kc) * 2048 + (size_t)nin * 16;
#pragma unroll
        for (int j = 0; j < 2; j++) {
            int kp = w8 * 2 + j;
            int kloc = kcb * 32 + kp * 2;
            unsigned h, l; cvt_pair(t[kloc][nl], t[kloc + 1][nl], h, l);
            oh[base + kp] = h; ol[base + kp] = l;
        }
    }
}

// ------------------------- mma.sync GEMM: 128x128 tile, 512 threads, 32x32/warp -------------------------
// 16 warps in a 4(M) x 4(N) grid, BK=32 (16 kpairs), bf16x3 (HH+HL+LH),
// 4-stage cp.async pipeline, ldmatrix fragment loads, __launch_bounds__ caps regs at 128.
// GELU=0: C fp32 += bias. GELU=1: gelu(C+bias) -> packed bf16 hi/lo words (A-format).
template <int GELU>
__global__ void __launch_bounds__(512, 1)
mma_gemm2(const unsigned* __restrict__ Ah, const unsigned* __restrict__ Al,
          long long a_z, int a_ld,
          const unsigned* __restrict__ Bh, const unsigned* __restrict__ Bl,
          const float* __restrict__ bias_base, int bias_stride,
          float* __restrict__ Cf, long long c_z, int c_ld,
          unsigned* __restrict__ Oh, unsigned* __restrict__ Ol,
          long long o_z, int o_ld,
          const int* __restrict__ te, int nKb, int NTtot) {
    int nt = blockIdx.x, mt = blockIdx.y, z = blockIdx.z;
    int expert = te ? te[mt] : z;
    if (expert < 0) return;

    extern __shared__ unsigned smw[];
    uint32_t sb = smem_u32(smw);
    int tid = threadIdx.x, lane = tid & 31, wid = tid >> 5;
    int wm = (wid & 3) * 32, wn = (wid >> 2) * 32;
    int mBase = mt * 128;

    const unsigned* Abase_h = Ah + (size_t)z * a_z + (size_t)mBase * a_ld;
    const unsigned* Abase_l = Al + (size_t)z * a_z + (size_t)mBase * a_ld;
    const unsigned* Bbase_h = Bh + (size_t)(expert * NTtot + nt) * nKb * 2048;
    const unsigned* Bbase_l = Bl + (size_t)(expert * NTtot + nt) * nKb * 2048;

    // copy decode: each array is 128 rows x 16 words = 512 x 16B chunks; 1 chunk/thread/array
    int rowC = tid >> 2, c4 = (tid & 3) * 4;

    auto issue = [&](int kb) {
        uint32_t st = sb + (uint32_t)((kb & (NSTG - 1)) * STG_W) * 4;
        cp16(st + (AH_OFF + rowC * RSTRIDE + c4) * 4,
             Abase_h + (size_t)rowC * a_ld + kb * 16 + c4);
        cp16(st + (AL_OFF + rowC * RSTRIDE + c4) * 4,
             Abase_l + (size_t)rowC * a_ld + kb * 16 + c4);
        cp16(st + (BH_OFF + rowC * RSTRIDE + c4) * 4,
             Bbase_h + (size_t)kb * 2048 + rowC * 16 + c4);
        cp16(st + (BL_OFF + rowC * RSTRIDE + c4) * 4,
             Bbase_l + (size_t)kb * 2048 + rowC * 16 + c4);
    };

    float acc[2][4][4];
#pragma unroll
    for (int a = 0; a < 2; a++)
#pragma unroll
        for (int b = 0; b < 4; b++)
#pragma unroll
            for (int c = 0; c < 4; c++) acc[a][b][c] = 0.f;

    // prologue: 3 stages in flight
#pragma unroll
    for (int s = 0; s < NSTG - 1; s++) {
        if (s < nKb) issue(s);
        CP_COMMIT();
    }

    // ldmatrix per-thread base offsets (bytes)
    uint32_t a_off = (uint32_t)((wm + (lane & 15)) * RSTRIDE + (lane >> 4) * 4) * 4;
    uint32_t b_off = (uint32_t)((wn + (lane & 7)) * RSTRIDE + ((lane >> 3) & 1) * 4) * 4;

    for (int kb = 0; kb < nKb; kb++) {
        CP_WAIT2();
        __syncthreads();
        int nx = kb + NSTG - 1;
        if (nx < nKb) issue(nx);
        CP_COMMIT();

        uint32_t stg = sb + (uint32_t)((kb & (NSTG - 1)) * STG_W) * 4;
        uint32_t aH = stg + AH_OFF * 4 + a_off;
        uint32_t aL = stg + AL_OFF * 4 + a_off;
        uint32_t bH = stg + BH_OFF * 4 + b_off;
        uint32_t bL = stg + BL_OFF * 4 + b_off;
#pragma unroll
        for (int ks = 0; ks < 2; ks++) {
            unsigned ah[2][4], al[2][4];
#pragma unroll
            for (int m2 = 0; m2 < 2; m2++) {
                uint32_t o = m2 * (16 * RSTRIDE * 4) + ks * 32;
                LDSM4(ah[m2][0], ah[m2][1], ah[m2][2], ah[m2][3], aH + o);
                LDSM4(al[m2][0], al[m2][1], al[m2][2], al[m2][3], aL + o);
            }
#pragma unroll
            for (int n8 = 0; n8 < 4; n8++) {
                unsigned bh[2], bl[2];
                uint32_t o = n8 * (8 * RSTRIDE * 4) + ks * 32;
                LDSM2(bh[0], bh[1], bH + o);
                LDSM2(bl[0], bl[1], bL + o);
#pragma unroll
                for (int m2 = 0; m2 < 2; m2++) MMA_BF16(acc[m2][n8], ah[m2], bh);
#pragma unroll
                for (int m2 = 0; m2 < 2; m2++) MMA_BF16(acc[m2][n8], ah[m2], bl);
#pragma unroll
                for (int m2 = 0; m2 < 2; m2++) MMA_BF16(acc[m2][n8], al[m2], bh);
            }
        }
    }

    // epilogue
    const float* bias = bias_base + (size_t)expert * bias_stride + nt * 128;
#pragma unroll
    for (int m2 = 0; m2 < 2; m2++) {
#pragma unroll
        for (int n8 = 0; n8 < 4; n8++) {
            int row0 = mBase + wm + m2 * 16 + (lane >> 2);
            int c0 = wn + n8 * 8 + (lane & 3) * 2;
            float b0 = bias[c0], b1 = bias[c0 + 1];
            float v0 = acc[m2][n8][0] + b0;
            float v1 = acc[m2][n8][1] + b1;
            float v2 = acc[m2][n8][2] + b0;
            float v3 = acc[m2][n8][3] + b1;
            if (GELU) {
                v0 = 0.5f * v0 * (1.0f + erff(v0 * 0.70710678118654752f));
                v1 = 0.5f * v1 * (1.0f + erff(v1 * 0.70710678118654752f));
                v2 = 0.5f * v2 * (1.0f + erff(v2 * 0.70710678118654752f));
                v3 = 0.5f * v3 * (1.0f + erff(v3 * 0.70710678118654752f));
                unsigned h0, l0, h1, l1;
                cvt_pair(v0, v1, h0, l0);
                cvt_pair(v2, v3, h1, l1);
                size_t w = (size_t)((nt * 128 + c0) >> 1);
                size_t b0i = (size_t)z * o_z + (size_t)row0 * o_ld + w;
                size_t b1i = b0i + (size_t)8 * o_ld;
                Oh[b0i] = h0; Ol[b0i] = l0;
                Oh[b1i] = h1; Ol[b1i] = l1;
            } else {
                size_t base = (size_t)z * c_z + (size_t)row0 * c_ld + nt * 128 + c0;
                *(float2*)&Cf[base] = make_float2(v0, v1);
                *(float2*)&Cf[base + (size_t)8 * c_ld] = make_float2(v2, v3);
            }
        }
    }
}

// ------------------------- final combine -------------------------
__global__ void combine_kernel(float* __restrict__ out, int N) {
    int idx = blockIdx.x * blockDim.x + threadIdx.x;
    int total = N * (DDIM / 4);
    if (idx >= total) return;
    int n = idx / (DDIM / 4);
    int d = (idx % (DDIM / 4)) * 4;
    const float4 s0 = *(const float4*)&g_ys[(size_t)n * DDIM + d];
    const float4 s1 = *(const float4*)&g_ys[(size_t)N * DDIM + (size_t)n * DDIM + d];
    int sl0 = g_slot_of[2 * n], sl1 = g_slot_of[2 * n + 1];
    float w0 = g_gate[2 * n], w1 = g_gate[2 * n + 1];
    const float4 y0 = *(const float4*)&g_ybuf[(size_t)sl0 * DDIM + d];
    const float4 y1 = *(const float4*)&g_ybuf[(size_t)sl1 * DDIM + d];
    const float inv_s = 1.0f / NSH;
    float4 o;
    o.x = inv_s * (s0.x + s1.x) + w0 * y0.x + w1 * y1.x;
    o.y = inv_s * (s0.y + s1.y) + w0 * y0.y + w1 * y1.y;
    o.z = inv_s * (s0.z + s1.z) + w0 * y0.z + w1 * y1.z;
    o.w = inv_s * (s0.w + s1.w) + w0 * y0.w + w1 * y1.w;
    *(float4*)&out[(size_t)n * DDIM + d] = o;
}

// ------------------------- launch -------------------------
#define SYM(p, s) void* p; cudaGetSymbolAddress(&p, s)

extern "C" void kernel_launch(void* const* d_in, const int* in_sizes, int n_in,
                              void* d_out, int out_size) {
    const float* x   = (const float*)d_in[0];
    const float* rw  = (const float*)d_in[1];
    const float* rb  = (const float*)d_in[2];
    const float* w1  = (const float*)d_in[3];
    const float* b1  = (const float*)d_in[4];
    const float* w2  = (const float*)d_in[5];
    const float* b2  = (const float*)d_in[6];
    const float* sw1 = (const float*)d_in[7];
    const float* sb1 = (const float*)d_in[8];
    const float* sw2 = (const float*)d_in[9];
    const float* sb2 = (const float*)d_in[10];
    float* out = (float*)d_out;
    int N = in_sizes[0] / DDIM;

    cudaFuncSetAttribute(mma_gemm2<0>, cudaFuncAttributeMaxDynamicSharedMemorySize, SMEMSZ);
    cudaFuncSetAttribute(mma_gemm2<1>, cudaFuncAttributeMaxDynamicSharedMemorySize, SMEMSZ);

    SYM(p_xh, g_x_hi);    SYM(p_xl, g_x_lo);
    SYM(p_gh, g_xg_hi);   SYM(p_gl, g_xg_lo);
    SYM(p_hh, g_h_hi);    SYM(p_hl, g_h_lo);
    SYM(p_sh, g_hs_hi);   SYM(p_sl, g_hs_lo);
    SYM(p_w1h, g_w1t_hi); SYM(p_w1l, g_w1t_lo);
    SYM(p_w2h, g_w2t_hi); SYM(p_w2l, g_w2t_lo);
    SYM(p_s1h, g_s1t_hi); SYM(p_s1l, g_s1t_lo);
    SYM(p_s2h, g_s2t_hi); SYM(p_s2l, g_s2t_lo);
    SYM(p_yb, g_ybuf);    SYM(p_ys, g_ys);
    SYM(p_te, g_tile_expert);

    // 1) router + bucketing
    router_kernel<<<(N + 7) / 8, 256>>>(x, rw, rb, N);
    bucket_kernel<<<1, 256>>>(N);
    // 2) operand pre-conversion
    pack_x_kernel<<<(NTOK * 512 + 255) / 256, 256>>>(x);
    pack_xg_kernel<<<(MAXP_PAD * 512 + 255) / 256, 256>>>(x);
    dim3 tb(32, 8);
    wt_kernel<<<dim3(HDIM / 32, DDIM / 64, NEXP), tb>>>(w1, (unsigned*)p_w1h, (unsigned*)p_w1l, DDIM, HDIM);
    wt_kernel<<<dim3(DDIM / 32, HDIM / 64, NEXP), tb>>>(w2, (unsigned*)p_w2h, (unsigned*)p_w2l, HDIM, DDIM);
    wt_kernel<<<dim3(HDIM / 32, DDIM / 64, NSH), tb>>>(sw1, (unsigned*)p_s1h, (unsigned*)p_s1l, DDIM, HDIM);
    wt_kernel<<<dim3(DDIM / 32, HDIM / 64, NSH), tb>>>(sw2, (unsigned*)p_s2h, (unsigned*)p_s2l, HDIM, DDIM);
    // 3) routed GEMM1: h = gelu(xg @ w1[e] + b1[e]) -> packed bf16 (A-format)
    mma_gemm2<1><<<dim3(HDIM / 128, TILES_MAX, 1), 512, SMEMSZ>>>(
        (unsigned*)p_gh, (unsigned*)p_gl, 0, 512,
        (unsigned*)p_w1h, (unsigned*)p_w1l, b1, HDIM,
        nullptr, 0, 0, (unsigned*)p_hh, (unsigned*)p_hl, 0, 1024,
        (const int*)p_te, DDIM / 32, HDIM / 128);
    // 4) routed GEMM2: y = h @ w2[e] + b2[e] -> fp32
    mma_gemm2<0><<<dim3(DDIM / 128, TILES_MAX, 1), 512, SMEMSZ>>>(
        (unsigned*)p_hh, (unsigned*)p_hl, 0, 1024,
        (unsigned*)p_w2h, (unsigned*)p_w2l, b2, DDIM,
        (float*)p_yb, 0, DDIM, nullptr, nullptr, 0, 0,
        (const int*)p_te, HDIM / 32, DDIM / 128);
    // 5) shared GEMM1: hs[s] = gelu(x @ sw1[s] + sb1[s]) -> packed bf16
    //    A (x) is the SAME for both shared experts -> a_z stride 0.
    mma_gemm2<1><<<dim3(HDIM / 128, MT_S, NSH), 512, SMEMSZ>>>(
        (unsigned*)p_xh, (unsigned*)p_xl, 0, 512,
        (unsigned*)p_s1h, (unsigned*)p_s1l, sb1, HDIM,
        nullptr, 0, 0, (unsigned*)p_sh, (unsigned*)p_sl, (long long)NTOK * 1024, 1024,
        nullptr, DDIM / 32, HDIM / 128);
    // 6) shared GEMM2: ys[s] = hs[s] @ sw2[s] + sb2[s] -> fp32
    mma_gemm2<0><<<dim3(DDIM / 128, MT_S, NSH), 512, SMEMSZ>>>(
        (unsigned*)p_sh, (unsigned*)p_sl, (long long)NTOK * 1024, 1024,
        (unsigned*)p_s2h, (unsigned*)p_s2l, sb2, DDIM,
        (float*)p_ys, (long long)NTOK * DDIM, DDIM, nullptr, nullptr, 0, 0,
        nullptr, HDIM / 32, DDIM / 128);
    // 7) combine
    combine_kernel<<<(N * (DDIM / 4) + 255) / 256, 256>>>(out, N);
}